// round 1
// baseline (speedup 1.0000x reference)
#include <cuda_runtime.h>
#include <cuda_bf16.h>
#include <math.h>

// Problem constants
#define BATCH   8
#define NFREQ   513          // N_FFT/2 + 1
#define NT      4096         // frames
#define NFFT    1024
#define NH      512          // NFFT/2 (complex IFFT size)
#define HOP     256
#define WIN     1024
#define PAD     384          // (WIN - HOP)/2
#define OUT_LEN 1048576      // (NT-1)*HOP + WIN - 2*PAD
#define ENV_EPS 1e-11f

// Scratch: windowed frames [B][T][WIN]  (134 MB)
__device__ float g_frames[(size_t)BATCH * NT * WIN];

// smem skew to kill bank conflicts on the bit-reversed final read
#define SKEW(i) ((i) + ((i) >> 4))
#define ZLEN 545   // SKEW(512) = 544, +1

// ---------------------------------------------------------------------------
// Kernel 1: build Z from half-spectrum, 512-pt inverse FFT (radix-2 DIF,
// warp-per-transform, 8 transforms/block for coalesced strided loads),
// window + 1/1024 scale, write frames.
// ---------------------------------------------------------------------------
__global__ __launch_bounds__(256) void istft_fft_kernel(
    const float* __restrict__ sr,   // (B, 513, 4096)
    const float* __restrict__ si,
    const float* __restrict__ win)  // (1024,)
{
    __shared__ float zr[8][ZLEN];
    __shared__ float zi[8][ZLEN];
    __shared__ float twr[512];
    __shared__ float twi[512];

    const int tid = threadIdx.x;

    // Twiddle table: for stage half-size h, tw[h+j] = e^{+i*pi*j/h}, j in [0,h)
    for (int idx = tid; idx < 512; idx += 256) {
        if (idx >= 1) {
            int h = 1 << (31 - __clz(idx));
            int j = idx - h;
            float s, c;
            __sincosf((float)M_PI * (float)j / (float)h, &s, &c);
            twr[idx] = c;
            twi[idx] = s;
        }
    }

    const int blk  = blockIdx.x;        // 0..4095
    const int b    = blk >> 9;          // batch
    const int tile = blk & 511;         // 8 frames per tile
    const size_t base = (size_t)b * NFREQ * NT + (size_t)tile * 8;

    // Cooperative coalesced load: e -> (t_local = e&7, k = e>>3)
    for (int e = tid; e < 8 * NFREQ; e += 256) {
        int tl = e & 7;
        int k  = e >> 3;
        size_t g = base + (size_t)k * NT + tl;
        zr[tl][SKEW(k)] = sr[g];
        zi[tl][SKEW(k)] = si[g];
    }
    __syncthreads();

    const int warp = tid >> 5;
    const int lane = tid & 31;
    float* Zr = zr[warp];
    float* Zi = zi[warp];

    // Build Z in place (pairs k, 512-k). Im of bins 0 and 512 dropped (c2r semantics).
    for (int k = lane; k <= 256; k += 32) {
        int k2 = 512 - k;
        float ar = Zr[SKEW(k)];
        float ai = (k == 0) ? 0.0f : Zi[SKEW(k)];
        float br = Zr[SKEW(k2)];
        float bi = (k == 0) ? 0.0f : -Zi[SKEW(k2)];   // conj(X[512-k])

        float er  = ar + br, ei  = ai + bi;
        float odr = ar - br, odi = ai - bi;
        float s, c;
        __sincosf((float)M_PI * (float)k * (1.0f / 512.0f), &s, &c); // e^{i*2pi*k/1024}
        float or_ = odr * c - odi * s;
        float oi  = odr * s + odi * c;

        // Z[k] = E + i*O
        Zr[SKEW(k)] = er - oi;
        Zi[SKEW(k)] = ei + or_;
        // Z[512-k] = conj(E) + i*conj(O)
        if (k > 0 && k < 256) {
            Zr[SKEW(k2)] = er + oi;
            Zi[SKEW(k2)] = or_ - ei;
        }
    }
    __syncwarp();

    // In-place radix-2 DIF inverse FFT (W = e^{+2pi i/512}); output bit-reversed.
    for (int h = 256; h >= 1; h >>= 1) {
        #pragma unroll 1
        for (int r = 0; r < 8; ++r) {
            int m  = lane + 32 * r;                  // butterfly id 0..255
            int j  = m & (h - 1);
            int i0 = ((m & ~(h - 1)) << 1) | j;      // g*2h + j
            int i1 = i0 + h;
            float ur = Zr[SKEW(i0)], ui = Zi[SKEW(i0)];
            float vr = Zr[SKEW(i1)], vi = Zi[SKEW(i1)];
            Zr[SKEW(i0)] = ur + vr;
            Zi[SKEW(i0)] = ui + vi;
            float dr = ur - vr, di = ui - vi;
            float wr = twr[h + j], wi = twi[h + j];
            Zr[SKEW(i1)] = dr * wr - di * wi;
            Zi[SKEW(i1)] = dr * wi + di * wr;
        }
        __syncwarp();
    }

    // Write windowed frame. z[n] = stored[bitrev9(n)]; x[2n]=Re, x[2n+1]=Im; scale 1/1024.
    const int t = tile * 8 + warp;
    float2* fout = (float2*)(g_frames + (((size_t)b * NT + t) << 10));
    const float2* w2 = (const float2*)win;
    for (int n = lane; n < 512; n += 32) {
        int rev = __brev(n) >> 23;
        float re = Zr[SKEW(rev)] * (1.0f / 1024.0f);
        float im = Zi[SKEW(rev)] * (1.0f / 1024.0f);
        float2 w = w2[n];
        float2 o;
        o.x = re * w.x;
        o.y = im * w.y;
        fout[n] = o;
    }
}

// ---------------------------------------------------------------------------
// Kernel 2: overlap-add gather + envelope divide + crop.
// Each thread handles one output position m for all 8 batches.
// ---------------------------------------------------------------------------
__global__ __launch_bounds__(256) void istft_ola_kernel(
    const float* __restrict__ win,
    float* __restrict__ out)
{
    int m = blockIdx.x * 256 + threadIdx.x;   // 0..OUT_LEN-1
    if (m >= OUT_LEN) return;
    int n = m + PAD;
    int q = n >> 8;
    int tlo = max(0, q - 3);
    int thi = min(NT - 1, q);

    float env = 0.0f;
    float acc[BATCH];
    #pragma unroll
    for (int b = 0; b < BATCH; ++b) acc[b] = 0.0f;

    for (int t = tlo; t <= thi; ++t) {
        int w = n - (t << 8);                 // 0..1023
        float wv = __ldg(&win[w]);
        env += wv * wv;
        #pragma unroll
        for (int b = 0; b < BATCH; ++b)
            acc[b] += g_frames[(((size_t)b * NT + t) << 10) + w];
    }

    float inv = 1.0f / fmaxf(env, ENV_EPS);
    #pragma unroll
    for (int b = 0; b < BATCH; ++b)
        out[(size_t)b * OUT_LEN + m] = acc[b] * inv;
}

// ---------------------------------------------------------------------------
extern "C" void kernel_launch(void* const* d_in, const int* in_sizes, int n_in,
                              void* d_out, int out_size)
{
    const float* spec_real = (const float*)d_in[0];
    const float* spec_imag = (const float*)d_in[1];
    const float* window    = (const float*)d_in[2];
    float* out = (float*)d_out;

    istft_fft_kernel<<<BATCH * (NT / 8), 256>>>(spec_real, spec_imag, window);
    istft_ola_kernel<<<OUT_LEN / 256, 256>>>(window, out);
}

// round 2
// speedup vs baseline: 1.2911x; 1.2911x over previous
#include <cuda_runtime.h>
#include <cuda_bf16.h>
#include <math.h>

// Problem constants
#define BATCH   8
#define NFREQ   513          // N_FFT/2 + 1
#define NT      4096         // frames
#define NFFT    1024
#define HOP     256
#define WIN     1024
#define PAD     384          // (WIN - HOP)/2
#define OUT_LEN 1048576      // (NT-1)*HOP + WIN - 2*PAD
#define ENV_EPS 1e-11f
#define FPI     3.14159265358979323846f

// Scratch: windowed frames [B][T][WIN]  (134 MB)
__device__ float g_frames[(size_t)BATCH * NT * WIN];

// ---------------------------------------------------------------------------
// 16-point inverse-sign (e^{+i...}) DFT, radix-2 DIF, in registers.
// Output is bit-reversed: storage slot p holds output index brev4(p).
// ---------------------------------------------------------------------------
__device__ __forceinline__ void ifft16(float xr[16], float xi[16])
{
    // stage h=8: twiddle e^{i*pi*j/8}
    constexpr float C8[8] = {1.0f, 0.92387953251128675f, 0.70710678118654752f,
                             0.38268343236508977f, 0.0f, -0.38268343236508977f,
                             -0.70710678118654752f, -0.92387953251128675f};
    constexpr float S8[8] = {0.0f, 0.38268343236508977f, 0.70710678118654752f,
                             0.92387953251128675f, 1.0f, 0.92387953251128675f,
                             0.70710678118654752f, 0.38268343236508977f};
    #pragma unroll
    for (int j = 0; j < 8; ++j) {
        float ur = xr[j], ui = xi[j], vr = xr[j+8], vi = xi[j+8];
        xr[j] = ur + vr; xi[j] = ui + vi;
        float dr = ur - vr, di = ui - vi;
        xr[j+8] = dr * C8[j] - di * S8[j];
        xi[j+8] = dr * S8[j] + di * C8[j];
    }
    // stage h=4: twiddle e^{i*pi*j/4}
    constexpr float C4[4] = {1.0f, 0.70710678118654752f, 0.0f, -0.70710678118654752f};
    constexpr float S4[4] = {0.0f, 0.70710678118654752f, 1.0f,  0.70710678118654752f};
    #pragma unroll
    for (int g = 0; g < 16; g += 8)
        #pragma unroll
        for (int j = 0; j < 4; ++j) {
            int i0 = g + j, i1 = i0 + 4;
            float ur = xr[i0], ui = xi[i0], vr = xr[i1], vi = xi[i1];
            xr[i0] = ur + vr; xi[i0] = ui + vi;
            float dr = ur - vr, di = ui - vi;
            xr[i1] = dr * C4[j] - di * S4[j];
            xi[i1] = dr * S4[j] + di * C4[j];
        }
    // stage h=2: twiddles 1, i
    #pragma unroll
    for (int g = 0; g < 16; g += 4) {
        { // j=0
            int i0 = g, i1 = g + 2;
            float ur = xr[i0], ui = xi[i0], vr = xr[i1], vi = xi[i1];
            xr[i0] = ur + vr; xi[i0] = ui + vi;
            xr[i1] = ur - vr; xi[i1] = ui - vi;
        }
        { // j=1: (dr + i di)*i = (-di, dr)
            int i0 = g + 1, i1 = g + 3;
            float ur = xr[i0], ui = xi[i0], vr = xr[i1], vi = xi[i1];
            xr[i0] = ur + vr; xi[i0] = ui + vi;
            float dr = ur - vr, di = ui - vi;
            xr[i1] = -di; xi[i1] = dr;
        }
    }
    // stage h=1: twiddle 1
    #pragma unroll
    for (int g = 0; g < 16; g += 2) {
        float ur = xr[g], ui = xi[g], vr = xr[g+1], vi = xi[g+1];
        xr[g] = ur + vr; xi[g] = ui + vi;
        xr[g+1] = ur - vr; xi[g+1] = ui - vi;
    }
}

// ---------------------------------------------------------------------------
// Kernel 1: Hermitian pack + 512-pt inverse complex FFT (register four-step:
// 16 in regs x 32 across lanes via shfl), window + scale, write frames.
// Warp per transform, 8 transforms/block for coalesced strided loads.
// ---------------------------------------------------------------------------
__global__ __launch_bounds__(256) void istft_fft_kernel(
    const float* __restrict__ sr,   // (B, 513, 4096)
    const float* __restrict__ si,
    const float* __restrict__ win)  // (1024,)
{
    __shared__ float zr[8][516];
    __shared__ float zi[8][516];

    const int tid  = threadIdx.x;
    const int blk  = blockIdx.x;        // 0..4095
    const int b    = blk >> 9;          // batch
    const int tile = blk & 511;         // 8 frames per tile
    const size_t base = (size_t)b * NFREQ * NT + (size_t)tile * 8;

    // Cooperative coalesced load: e -> (t_local = e&7, k = e>>3)
    for (int e = tid; e < 8 * NFREQ; e += 256) {
        int tl = e & 7;
        int k  = e >> 3;
        size_t g = base + (size_t)k * NT + tl;
        zr[tl][k] = sr[g];
        zi[tl][k] = si[g];
    }
    __syncthreads();

    const int warp = tid >> 5;
    const int lane = tid & 31;
    float* Zr = zr[warp];
    float* Zi = zi[warp];

    // Hermitian pack: Z[k] = E[k] + i*O[k], Z[512-k] = conj(E) + i*conj(O).
    // Im of bins 0 and 512 dropped (c2r semantics).
    for (int k = lane; k <= 256; k += 32) {
        int k2 = 512 - k;
        float ar = Zr[k];
        float ai = (k == 0) ? 0.0f : Zi[k];
        float br = Zr[k2];
        float bi = (k == 0) ? 0.0f : -Zi[k2];   // conj(X[512-k])

        float er  = ar + br, ei  = ai + bi;
        float odr = ar - br, odi = ai - bi;
        float s, c;
        __sincosf(FPI * (float)k * (1.0f / 512.0f), &s, &c);
        float or_ = odr * c - odi * s;
        float oi  = odr * s + odi * c;

        Zr[k] = er - oi;
        Zi[k] = ei + or_;
        if (k > 0 && k < 256) {
            Zr[k2] = er + oi;
            Zi[k2] = or_ - ei;
        }
    }
    __syncwarp();

    // Load registers: lane l holds Z[l + 32*j], j=0..15  (conflict-free)
    float xr[16], xi[16];
    #pragma unroll
    for (int j = 0; j < 16; ++j) {
        xr[j] = Zr[lane + 32*j];
        xi[j] = Zi[lane + 32*j];
    }

    // Step A: 16-pt DFT over j (sign +i). Output bit-reversed in slots.
    ifft16(xr, xi);

    // Reorder to natural n2 order + Step B twiddle e^{+i*pi*lane*n2/256}
    constexpr int BR4[16] = {0,8,4,12,2,10,6,14,1,9,5,13,3,11,7,15};
    float yr[16], yi[16];
    #pragma unroll
    for (int p = 0; p < 16; ++p) {
        yr[BR4[p]] = xr[p];
        yi[BR4[p]] = xi[p];
    }
    const float a = FPI * (1.0f / 256.0f) * (float)lane;
    #pragma unroll
    for (int n2 = 1; n2 < 16; ++n2) {
        float s, c;
        __sincosf(a * (float)n2, &s, &c);
        float tr = yr[n2] * c - yi[n2] * s;
        float ti = yr[n2] * s + yi[n2] * c;
        yr[n2] = tr; yi[n2] = ti;
    }

    // Step C: 32-pt DFT across lanes (sign +i), radix-2 DIF via shfl_xor.
    #pragma unroll
    for (int st = 0; st < 5; ++st) {
        const int h = 16 >> st;
        const int j = lane & (h - 1);
        float ws, wc;
        __sincosf(FPI * (float)j / (float)h, &ws, &wc);
        const bool up = (lane & h) != 0;
        #pragma unroll
        for (int n2 = 0; n2 < 16; ++n2) {
            float pr = __shfl_xor_sync(0xffffffffu, yr[n2], h);
            float pi = __shfl_xor_sync(0xffffffffu, yi[n2], h);
            float sr_ = yr[n2] + pr, si_ = yi[n2] + pi;
            float dr  = pr - yr[n2], di  = pi - yi[n2];
            float tr  = dr * wc - di * ws;
            float ti  = dr * ws + di * wc;
            yr[n2] = up ? tr : sr_;
            yi[n2] = up ? ti : si_;
        }
    }

    // lane holds z[16*brev5(lane) + n2]. Even/odd unpack: x[2n]=Re, x[2n+1]=Im.
    // -> 32 consecutive output samples starting at 32*n1. Window + 1/1024 scale.
    const int n1 = __brev(lane) >> 27;
    const int t  = tile * 8 + warp;
    float4* fout = (float4*)(g_frames + (((size_t)b * NT + t) << 10) + 32 * n1);
    const float4* w4 = (const float4*)(win + 32 * n1);
    constexpr float SC = 1.0f / 1024.0f;
    #pragma unroll
    for (int q = 0; q < 8; ++q) {
        float4 w = __ldg(&w4[q]);
        float4 o;
        o.x = yr[2*q]   * SC * w.x;
        o.y = yi[2*q]   * SC * w.y;
        o.z = yr[2*q+1] * SC * w.z;
        o.w = yi[2*q+1] * SC * w.w;
        fout[q] = o;
    }
}

// ---------------------------------------------------------------------------
// Kernel 2: overlap-add gather + envelope divide + crop. 4 outputs/thread,
// all frame traffic as float4 (frame boundaries align with the 4-vector).
// ---------------------------------------------------------------------------
__global__ __launch_bounds__(256) void istft_ola_kernel(
    const float* __restrict__ win,
    float* __restrict__ out)
{
    int v = blockIdx.x * 256 + threadIdx.x;   // 0 .. OUT_LEN/4 - 1
    int m0 = v * 4;
    int n0 = m0 + PAD;                        // multiple of 4
    int nhi = n0 + 3;
    int thi = min(NT - 1, nhi >> 8);
    int tlo = max(0, (nhi >> 8) - 3);

    float ex = 0.f, ey = 0.f, ez = 0.f, ew = 0.f;
    float4 acc[BATCH];
    #pragma unroll
    for (int b = 0; b < BATCH; ++b) acc[b] = make_float4(0.f, 0.f, 0.f, 0.f);

    for (int t = tlo; t <= thi; ++t) {
        int w0 = n0 - (t << 8);               // multiple of 4
        if (w0 < 0 || w0 > WIN - 4) continue; // all-or-nothing for the 4-vector
        float4 w = __ldg((const float4*)(win + w0));
        ex += w.x * w.x; ey += w.y * w.y; ez += w.z * w.z; ew += w.w * w.w;
        #pragma unroll
        for (int b = 0; b < BATCH; ++b) {
            float4 f = *(const float4*)(g_frames + ((((size_t)b * NT + t) << 10) + w0));
            acc[b].x += f.x; acc[b].y += f.y; acc[b].z += f.z; acc[b].w += f.w;
        }
    }

    float ix = 1.0f / fmaxf(ex, ENV_EPS);
    float iy = 1.0f / fmaxf(ey, ENV_EPS);
    float iz = 1.0f / fmaxf(ez, ENV_EPS);
    float iw = 1.0f / fmaxf(ew, ENV_EPS);
    #pragma unroll
    for (int b = 0; b < BATCH; ++b) {
        float4 o;
        o.x = acc[b].x * ix;
        o.y = acc[b].y * iy;
        o.z = acc[b].z * iz;
        o.w = acc[b].w * iw;
        *(float4*)(out + (size_t)b * OUT_LEN + m0) = o;
    }
}

// ---------------------------------------------------------------------------
extern "C" void kernel_launch(void* const* d_in, const int* in_sizes, int n_in,
                              void* d_out, int out_size)
{
    const float* spec_real = (const float*)d_in[0];
    const float* spec_imag = (const float*)d_in[1];
    const float* window    = (const float*)d_in[2];
    float* out = (float*)d_out;

    istft_fft_kernel<<<BATCH * (NT / 8), 256>>>(spec_real, spec_imag, window);
    istft_ola_kernel<<<OUT_LEN / 4 / 256, 256>>>(window, out);
}

// round 3
// speedup vs baseline: 1.4778x; 1.1446x over previous
#include <cuda_runtime.h>
#include <cuda_bf16.h>
#include <math.h>

// Problem constants
#define BATCH   8
#define NFREQ   513          // N_FFT/2 + 1
#define NT      4096         // frames
#define HOP     256
#define WIN     1024
#define PAD     384          // (WIN - HOP)/2
#define OUT_LEN 1048576      // (NT-1)*HOP + WIN - 2*PAD
#define ENV_EPS 1e-11f
#define FPI     3.14159265358979323846f
#define R2      0.70710678118654752f

// Scratch: windowed frames [B][T][WIN]  (134 MB)
__device__ float g_frames[(size_t)BATCH * NT * WIN];

__device__ __forceinline__ float2 cmul(float2 a, float2 b) {
    return make_float2(a.x * b.x - a.y * b.y, a.x * b.y + a.y * b.x);
}

// 8-point DFT with sign +i (inverse), radix-2 DIF, in registers.
// Output bit-reversed: slot p holds output index brev3(p) = {0,4,2,6,1,5,3,7}[p].
__device__ __forceinline__ void idft8(float2 x[8])
{
    float2 u, v, d;
    // stage h=4, twiddle e^{+i pi j/4}
    u = x[0]; v = x[4];
    x[0] = make_float2(u.x + v.x, u.y + v.y);
    x[4] = make_float2(u.x - v.x, u.y - v.y);
    u = x[1]; v = x[5]; d = make_float2(u.x - v.x, u.y - v.y);
    x[1] = make_float2(u.x + v.x, u.y + v.y);
    x[5] = make_float2(R2 * (d.x - d.y), R2 * (d.x + d.y));          // * (R2 + i R2)
    u = x[2]; v = x[6]; d = make_float2(u.x - v.x, u.y - v.y);
    x[2] = make_float2(u.x + v.x, u.y + v.y);
    x[6] = make_float2(-d.y, d.x);                                    // * i
    u = x[3]; v = x[7]; d = make_float2(u.x - v.x, u.y - v.y);
    x[3] = make_float2(u.x + v.x, u.y + v.y);
    x[7] = make_float2(-R2 * (d.x + d.y), R2 * (d.x - d.y));          // * (-R2 + i R2)
    // stage h=2, twiddles 1, i
    #pragma unroll
    for (int g = 0; g < 8; g += 4) {
        u = x[g]; v = x[g + 2];
        x[g]     = make_float2(u.x + v.x, u.y + v.y);
        x[g + 2] = make_float2(u.x - v.x, u.y - v.y);
        u = x[g + 1]; v = x[g + 3]; d = make_float2(u.x - v.x, u.y - v.y);
        x[g + 1] = make_float2(u.x + v.x, u.y + v.y);
        x[g + 3] = make_float2(-d.y, d.x);                            // * i
    }
    // stage h=1
    #pragma unroll
    for (int g = 0; g < 8; g += 2) {
        u = x[g]; v = x[g + 1];
        x[g]     = make_float2(u.x + v.x, u.y + v.y);
        x[g + 1] = make_float2(u.x - v.x, u.y - v.y);
    }
}

// ---------------------------------------------------------------------------
// Kernel 1: Hermitian pack + 512-pt inverse FFT (3 x radix-8 Stockham,
// 64 threads/transform, 8 transforms per 512-thread block), window + scale.
// ---------------------------------------------------------------------------
#define TSTRIDE 583   // float2 stride per transform (odd-ish padding)

__global__ __launch_bounds__(512) void istft_fft_kernel(
    const float* __restrict__ sr,   // (B, 513, 4096)
    const float* __restrict__ si,
    const float* __restrict__ win)  // (1024,)
{
    __shared__ float2 Sm[8][TSTRIDE];   // per-transform work buffer (>=575 used)
    __shared__ float2 TW[1024];         // e^{+2 pi i x / 1024}

    const int tid = threadIdx.x;

    // Twiddle table
    #pragma unroll
    for (int i = tid; i < 1024; i += 512) {
        float s, c;
        __sincosf((2.0f * FPI / 1024.0f) * (float)i, &s, &c);
        TW[i] = make_float2(c, s);
    }

    const int blk  = blockIdx.x;        // 0..4095
    const int b    = blk >> 9;          // batch
    const int tile = blk & 511;         // 8 frames per tile
    const size_t base = (size_t)b * NFREQ * NT + (size_t)tile * 8;

    // Coalesced global load: e -> (tl = e&7, k = e>>3); 32B sectors fully used.
    for (int e = tid; e < 8 * NFREQ; e += 512) {
        int tl = e & 7;
        int k  = e >> 3;
        size_t g = base + (size_t)k * NT + tl;
        Sm[tl][k] = make_float2(sr[g], si[g]);
    }
    __syncthreads();

    const int u  = tid & 63;    // thread within transform
    const int tr = tid >> 6;    // transform 0..7
    float2* S = Sm[tr];

    // Hermitian pack: Z[k] = E + iO, Z[512-k] = conj(E) + i conj(O).
    // Im of bins 0 and 512 dropped (c2r semantics).
    #pragma unroll
    for (int j = 0; j < 5; ++j) {
        int k = u + 64 * j;
        if (j == 4) { if (u != 0) break; k = 256; }
        float2 Xa = S[k];
        float2 Xb = S[512 - k];
        float ar = Xa.x, ai = (k == 0) ? 0.0f : Xa.y;
        float br = Xb.x, bi = (k == 0) ? 0.0f : -Xb.y;
        float er  = ar + br, ei  = ai + bi;
        float odr = ar - br, odi = ai - bi;
        float2 t = TW[k];                    // e^{+i pi k/512}
        float or_ = odr * t.x - odi * t.y;
        float oi  = odr * t.y + odi * t.x;
        S[k] = make_float2(er - oi, ei + or_);
        if (k > 0 && k < 256)
            S[512 - k] = make_float2(er + oi, or_ - ei);
    }
    __syncthreads();

    constexpr int BR3[8] = {0, 4, 2, 6, 1, 5, 3, 7};

    // ---- Stage 1: DFT-8 over k2 (stride 64). Thread u = j = k0 + 8*k1.
    {
        float2 x[8];
        #pragma unroll
        for (int k2 = 0; k2 < 8; ++k2) x[k2] = S[u + 64 * k2];
        idft8(x);
        __syncthreads();                    // all reads done before overwrites
        #pragma unroll
        for (int p = 0; p < 8; ++p) S[9 * u + BR3[p]] = x[p];  // A[j][n2]
        __syncthreads();
    }

    // ---- Stage 2: twiddle w64^{n2*k1}, DFT-8 over k1. Thread u = n2 + 8*k0.
    {
        const int n2 = u & 7;
        const int k0 = u >> 3;
        float2 a[8];
        #pragma unroll
        for (int k1 = 0; k1 < 8; ++k1) a[k1] = S[9 * (k0 + 8 * k1) + n2];
        #pragma unroll
        for (int k1 = 1; k1 < 8; ++k1)
            a[k1] = cmul(a[k1], TW[(16 * n2 * k1) & 1023]);
        idft8(a);
        __syncthreads();
        #pragma unroll
        for (int p = 0; p < 8; ++p)
            S[9 * (n2 + 8 * BR3[p]) + k0] = a[p];   // B[m = n2+8*n1][k0]
        __syncthreads();
    }

    // ---- Stage 3: twiddle w512^{m*k0}, DFT-8 over k0. Thread m = u.
    {
        const int m = u;
        float2 c[8];
        #pragma unroll
        for (int k0 = 0; k0 < 8; ++k0) c[k0] = S[9 * m + k0];
        #pragma unroll
        for (int k0 = 1; k0 < 8; ++k0)
            c[k0] = cmul(c[k0], TW[(2 * m * k0) & 1023]);
        idft8(c);

        // z[n], n = m + 64*n0. Even/odd unpack: x[2n]=Re, x[2n+1]=Im.
        const int t = tile * 8 + tr;
        float2* fout = (float2*)(g_frames + (((size_t)b * NT + t) << 10));
        const float2* w2 = (const float2*)win;
        constexpr float SC = 1.0f / 1024.0f;
        #pragma unroll
        for (int p = 0; p < 8; ++p) {
            int n = m + 64 * BR3[p];
            float2 w = __ldg(&w2[n]);
            fout[n] = make_float2(c[p].x * SC * w.x, c[p].y * SC * w.y);
        }
    }
}

// ---------------------------------------------------------------------------
// Kernel 2: overlap-add gather + envelope divide + crop (scalar, high-occ).
// ---------------------------------------------------------------------------
__global__ __launch_bounds__(256) void istft_ola_kernel(
    const float* __restrict__ win,
    float* __restrict__ out)
{
    int m = blockIdx.x * 256 + threadIdx.x;   // 0..OUT_LEN-1
    if (m >= OUT_LEN) return;
    int n = m + PAD;
    int q = n >> 8;
    int tlo = max(0, q - 3);
    int thi = min(NT - 1, q);

    float env = 0.0f;
    float acc[BATCH];
    #pragma unroll
    for (int b = 0; b < BATCH; ++b) acc[b] = 0.0f;

    for (int t = tlo; t <= thi; ++t) {
        int w = n - (t << 8);                 // 0..1023
        float wv = __ldg(&win[w]);
        env += wv * wv;
        #pragma unroll
        for (int b = 0; b < BATCH; ++b)
            acc[b] += g_frames[(((size_t)b * NT + t) << 10) + w];
    }

    float inv = 1.0f / fmaxf(env, ENV_EPS);
    #pragma unroll
    for (int b = 0; b < BATCH; ++b)
        out[(size_t)b * OUT_LEN + m] = acc[b] * inv;
}

// ---------------------------------------------------------------------------
extern "C" void kernel_launch(void* const* d_in, const int* in_sizes, int n_in,
                              void* d_out, int out_size)
{
    const float* spec_real = (const float*)d_in[0];
    const float* spec_imag = (const float*)d_in[1];
    const float* window    = (const float*)d_in[2];
    float* out = (float*)d_out;

    istft_fft_kernel<<<BATCH * (NT / 8), 512>>>(spec_real, spec_imag, window);
    istft_ola_kernel<<<OUT_LEN / 256, 256>>>(window, out);
}

// round 4
// speedup vs baseline: 2.0358x; 1.3776x over previous
#include <cuda_runtime.h>
#include <cuda_bf16.h>
#include <math.h>

// Problem constants
#define BATCH   8
#define NFREQ   513          // N_FFT/2 + 1
#define NT      4096         // frames
#define HOP     256
#define WIN     1024
#define PAD     384          // (WIN - HOP)/2
#define OUT_LEN 1048576      // (NT-1)*HOP + WIN - 2*PAD
#define ENV_EPS 1e-11f
#define FPI     3.14159265358979323846f
#define R2      0.70710678118654752f

// Scratch: windowed frames [B][T][WIN]  (134 MB)
__device__ float g_frames[(size_t)BATCH * NT * WIN];

__device__ __forceinline__ float2 cmul(float2 a, float2 b) {
    return make_float2(a.x * b.x - a.y * b.y, a.x * b.y + a.y * b.x);
}

// 8-point DFT with sign +i (inverse), radix-2 DIF, in registers.
// Output bit-reversed: slot p holds output index brev3(p) = {0,4,2,6,1,5,3,7}[p].
__device__ __forceinline__ void idft8(float2 x[8])
{
    float2 u, v, d;
    // stage h=4, twiddle e^{+i pi j/4}
    u = x[0]; v = x[4];
    x[0] = make_float2(u.x + v.x, u.y + v.y);
    x[4] = make_float2(u.x - v.x, u.y - v.y);
    u = x[1]; v = x[5]; d = make_float2(u.x - v.x, u.y - v.y);
    x[1] = make_float2(u.x + v.x, u.y + v.y);
    x[5] = make_float2(R2 * (d.x - d.y), R2 * (d.x + d.y));          // * (R2 + i R2)
    u = x[2]; v = x[6]; d = make_float2(u.x - v.x, u.y - v.y);
    x[2] = make_float2(u.x + v.x, u.y + v.y);
    x[6] = make_float2(-d.y, d.x);                                    // * i
    u = x[3]; v = x[7]; d = make_float2(u.x - v.x, u.y - v.y);
    x[3] = make_float2(u.x + v.x, u.y + v.y);
    x[7] = make_float2(-R2 * (d.x + d.y), R2 * (d.x - d.y));          // * (-R2 + i R2)
    // stage h=2, twiddles 1, i
    #pragma unroll
    for (int g = 0; g < 8; g += 4) {
        u = x[g]; v = x[g + 2];
        x[g]     = make_float2(u.x + v.x, u.y + v.y);
        x[g + 2] = make_float2(u.x - v.x, u.y - v.y);
        u = x[g + 1]; v = x[g + 3]; d = make_float2(u.x - v.x, u.y - v.y);
        x[g + 1] = make_float2(u.x + v.x, u.y + v.y);
        x[g + 3] = make_float2(-d.y, d.x);                            // * i
    }
    // stage h=1
    #pragma unroll
    for (int g = 0; g < 8; g += 2) {
        u = x[g]; v = x[g + 1];
        x[g]     = make_float2(u.x + v.x, u.y + v.y);
        x[g + 1] = make_float2(u.x - v.x, u.y - v.y);
    }
}

// ---------------------------------------------------------------------------
// Kernel 1: fused Hermitian pack + 512-pt inverse FFT (3 x radix-8 Stockham,
// 64 threads/transform, 8 transforms per 512-thread block), window + scale.
// Twiddles for stages 2/3 via per-thread sincos + power recurrence (no smem).
// ---------------------------------------------------------------------------
#define TSTRIDE 583   // float2 stride per transform

__global__ __launch_bounds__(512) void istft_fft_kernel(
    const float* __restrict__ sr,   // (B, 513, 4096)
    const float* __restrict__ si,
    const float* __restrict__ win)  // (1024,)
{
    __shared__ float2 Sm[8][TSTRIDE];   // per-transform work buffer
    __shared__ float2 TWH[257];         // e^{+i pi k / 512}, k = 0..256 (CF reads)

    const int tid = threadIdx.x;

    if (tid < 257) {
        float s, c;
        __sincosf((FPI / 512.0f) * (float)tid, &s, &c);
        TWH[tid] = make_float2(c, s);
    }

    const int blk  = blockIdx.x;        // 0..4095
    const int b    = blk >> 9;          // batch
    const int tile = blk & 511;         // 8 frames per tile
    const size_t base = (size_t)b * NFREQ * NT + (size_t)tile * 8;

    // Coalesced global load: e -> (tl = e&7, k = e>>3)
    for (int e = tid; e < 8 * NFREQ; e += 512) {
        int tl = e & 7;
        int k  = e >> 3;
        size_t g = base + (size_t)k * NT + tl;
        Sm[tl][k] = make_float2(sr[g], si[g]);
    }
    __syncthreads();

    const int u  = tid & 63;    // thread within transform
    const int tr = tid >> 6;    // transform 0..7
    float2* S = Sm[tr];

    constexpr int BR3[8] = {0, 4, 2, 6, 1, 5, 3, 7};

    // ---- Stage 1: Hermitian pack on the fly + DFT-8 over k2 (stride 64).
    // Z[k] = E + iO (k<=256);  Z[k] = conj(E) + i conj(O) (k>256), E/O at kk=512-k.
    // Im of bins 0 and 512 dropped (c2r semantics): only kk==0 masks imag.
    {
        float2 x[8];
        #pragma unroll
        for (int k2 = 0; k2 < 8; ++k2) {
            int k  = u + 64 * k2;
            int kk = (k <= 256) ? k : 512 - k;
            float2 Xa = S[kk];
            float2 Xb = S[512 - kk];
            float ar = Xa.x, ai = (kk == 0) ? 0.0f : Xa.y;
            float br = Xb.x, bi = (kk == 0) ? 0.0f : -Xb.y;
            float er  = ar + br, ei  = ai + bi;
            float odr = ar - br, odi = ai - bi;
            float2 t = TWH[kk];
            float or_ = odr * t.x - odi * t.y;
            float oi  = odr * t.y + odi * t.x;
            x[k2] = (k <= 256) ? make_float2(er - oi, ei + or_)
                               : make_float2(er + oi, or_ - ei);
        }
        idft8(x);
        __syncthreads();                    // raw reads done before overwrite
        #pragma unroll
        for (int p = 0; p < 8; ++p) S[9 * u + BR3[p]] = x[p];  // A[j][n2]
        __syncthreads();
    }

    // ---- Stage 2: twiddle w^{k1}, w = e^{2 pi i n2/64}; DFT-8 over k1.
    {
        const int n2 = u & 7;
        const int k0 = u >> 3;
        float2 a[8];
        #pragma unroll
        for (int k1 = 0; k1 < 8; ++k1) a[k1] = S[9 * (k0 + 8 * k1) + n2];
        float ws, wc;
        __sincosf((2.0f * FPI / 64.0f) * (float)n2, &ws, &wc);
        float2 w  = make_float2(wc, ws);
        float2 wk = w;
        a[1] = cmul(a[1], wk);
        #pragma unroll
        for (int k1 = 2; k1 < 8; ++k1) {
            wk = cmul(wk, w);
            a[k1] = cmul(a[k1], wk);
        }
        idft8(a);
        __syncthreads();
        #pragma unroll
        for (int p = 0; p < 8; ++p)
            S[9 * (n2 + 8 * BR3[p]) + k0] = a[p];   // B[m = n2+8*n1][k0]
        __syncthreads();
    }

    // ---- Stage 3: twiddle w^{k0}, w = e^{2 pi i m/512}; DFT-8 over k0.
    {
        const int m = u;
        float2 c[8];
        #pragma unroll
        for (int k0 = 0; k0 < 8; ++k0) c[k0] = S[9 * m + k0];
        float ws, wc;
        __sincosf((2.0f * FPI / 512.0f) * (float)m, &ws, &wc);
        float2 w  = make_float2(wc, ws);
        float2 wk = w;
        c[1] = cmul(c[1], wk);
        #pragma unroll
        for (int k0 = 2; k0 < 8; ++k0) {
            wk = cmul(wk, w);
            c[k0] = cmul(c[k0], wk);
        }
        idft8(c);

        // z[n], n = m + 64*n0. Even/odd unpack: x[2n]=Re, x[2n+1]=Im.
        const int t = tile * 8 + tr;
        float2* fout = (float2*)(g_frames + (((size_t)b * NT + t) << 10));
        const float2* w2 = (const float2*)win;
        constexpr float SC = 1.0f / 1024.0f;
        #pragma unroll
        for (int p = 0; p < 8; ++p) {
            int n = m + 64 * BR3[p];
            float2 wv = __ldg(&w2[n]);
            fout[n] = make_float2(c[p].x * SC * wv.x, c[p].y * SC * wv.y);
        }
    }
}

// ---------------------------------------------------------------------------
// Kernel 2: overlap-add gather + envelope divide + crop (scalar, high-occ).
// ---------------------------------------------------------------------------
__global__ __launch_bounds__(256) void istft_ola_kernel(
    const float* __restrict__ win,
    float* __restrict__ out)
{
    int m = blockIdx.x * 256 + threadIdx.x;   // 0..OUT_LEN-1
    if (m >= OUT_LEN) return;
    int n = m + PAD;
    int q = n >> 8;
    int tlo = max(0, q - 3);
    int thi = min(NT - 1, q);

    float env = 0.0f;
    float acc[BATCH];
    #pragma unroll
    for (int b = 0; b < BATCH; ++b) acc[b] = 0.0f;

    for (int t = tlo; t <= thi; ++t) {
        int w = n - (t << 8);                 // 0..1023
        float wv = __ldg(&win[w]);
        env += wv * wv;
        #pragma unroll
        for (int b = 0; b < BATCH; ++b)
            acc[b] += g_frames[(((size_t)b * NT + t) << 10) + w];
    }

    float inv = 1.0f / fmaxf(env, ENV_EPS);
    #pragma unroll
    for (int b = 0; b < BATCH; ++b)
        out[(size_t)b * OUT_LEN + m] = acc[b] * inv;
}

// ---------------------------------------------------------------------------
extern "C" void kernel_launch(void* const* d_in, const int* in_sizes, int n_in,
                              void* d_out, int out_size)
{
    const float* spec_real = (const float*)d_in[0];
    const float* spec_imag = (const float*)d_in[1];
    const float* window    = (const float*)d_in[2];
    float* out = (float*)d_out;

    istft_fft_kernel<<<BATCH * (NT / 8), 512>>>(spec_real, spec_imag, window);
    istft_ola_kernel<<<OUT_LEN / 256, 256>>>(window, out);
}

// round 5
// speedup vs baseline: 2.0384x; 1.0013x over previous
#include <cuda_runtime.h>
#include <cuda_bf16.h>
#include <cuda_fp16.h>
#include <math.h>

// Problem constants
#define BATCH   8
#define NFREQ   513          // N_FFT/2 + 1
#define NT      4096         // frames
#define HOP     256
#define WIN     1024
#define PAD     384          // (WIN - HOP)/2
#define OUT_LEN 1048576      // (NT-1)*HOP + WIN - 2*PAD
#define ENV_EPS 1e-11f
#define FPI     3.14159265358979323846f
#define R2      0.70710678118654752f

// Scratch: windowed frames [B][T][WIN] in fp16 (67 MB)
__device__ __half g_frames[(size_t)BATCH * NT * WIN];

__device__ __forceinline__ float2 cmul(float2 a, float2 b) {
    return make_float2(a.x * b.x - a.y * b.y, a.x * b.y + a.y * b.x);
}

// 8-point DFT with sign +i (inverse), radix-2 DIF, in registers.
// Output bit-reversed: slot p holds output index brev3(p) = {0,4,2,6,1,5,3,7}[p].
__device__ __forceinline__ void idft8(float2 x[8])
{
    float2 u, v, d;
    // stage h=4, twiddle e^{+i pi j/4}
    u = x[0]; v = x[4];
    x[0] = make_float2(u.x + v.x, u.y + v.y);
    x[4] = make_float2(u.x - v.x, u.y - v.y);
    u = x[1]; v = x[5]; d = make_float2(u.x - v.x, u.y - v.y);
    x[1] = make_float2(u.x + v.x, u.y + v.y);
    x[5] = make_float2(R2 * (d.x - d.y), R2 * (d.x + d.y));          // * (R2 + i R2)
    u = x[2]; v = x[6]; d = make_float2(u.x - v.x, u.y - v.y);
    x[2] = make_float2(u.x + v.x, u.y + v.y);
    x[6] = make_float2(-d.y, d.x);                                    // * i
    u = x[3]; v = x[7]; d = make_float2(u.x - v.x, u.y - v.y);
    x[3] = make_float2(u.x + v.x, u.y + v.y);
    x[7] = make_float2(-R2 * (d.x + d.y), R2 * (d.x - d.y));          // * (-R2 + i R2)
    // stage h=2, twiddles 1, i
    #pragma unroll
    for (int g = 0; g < 8; g += 4) {
        u = x[g]; v = x[g + 2];
        x[g]     = make_float2(u.x + v.x, u.y + v.y);
        x[g + 2] = make_float2(u.x - v.x, u.y - v.y);
        u = x[g + 1]; v = x[g + 3]; d = make_float2(u.x - v.x, u.y - v.y);
        x[g + 1] = make_float2(u.x + v.x, u.y + v.y);
        x[g + 3] = make_float2(-d.y, d.x);                            // * i
    }
    // stage h=1
    #pragma unroll
    for (int g = 0; g < 8; g += 2) {
        u = x[g]; v = x[g + 1];
        x[g]     = make_float2(u.x + v.x, u.y + v.y);
        x[g + 1] = make_float2(u.x - v.x, u.y - v.y);
    }
}

// ---------------------------------------------------------------------------
// Kernel 1: fused Hermitian pack + 512-pt inverse FFT (3 x radix-8 Stockham,
// 64 threads/transform, 8 transforms per 512-thread block), window + scale,
// fp16 frame output. __launch_bounds__(512,3) to lift occupancy to 48 warps/SM.
// ---------------------------------------------------------------------------
#define TSTRIDE 583   // float2 stride per transform

__global__ void __launch_bounds__(512, 3) istft_fft_kernel(
    const float* __restrict__ sr,   // (B, 513, 4096)
    const float* __restrict__ si,
    const float* __restrict__ win)  // (1024,)
{
    __shared__ float2 Sm[8][TSTRIDE];   // per-transform work buffer
    __shared__ float2 TWH[257];         // e^{+i pi k / 512}, k = 0..256

    const int tid = threadIdx.x;

    if (tid < 257) {
        float s, c;
        __sincosf((FPI / 512.0f) * (float)tid, &s, &c);
        TWH[tid] = make_float2(c, s);
    }

    const int blk  = blockIdx.x;        // 0..4095
    const int b    = blk >> 9;          // batch
    const int tile = blk & 511;         // 8 frames per tile
    const size_t base = (size_t)b * NFREQ * NT + (size_t)tile * 8;

    // Coalesced global load: e -> (tl = e&7, k = e>>3)
    for (int e = tid; e < 8 * NFREQ; e += 512) {
        int tl = e & 7;
        int k  = e >> 3;
        size_t g = base + (size_t)k * NT + tl;
        Sm[tl][k] = make_float2(sr[g], si[g]);
    }
    __syncthreads();

    const int u  = tid & 63;    // thread within transform
    const int tr = tid >> 6;    // transform 0..7
    float2* S = Sm[tr];

    constexpr int BR3[8] = {0, 4, 2, 6, 1, 5, 3, 7};

    // ---- Stage 1: Hermitian pack on the fly + DFT-8 over k2 (stride 64).
    // Z[k] = E + iO (k<=256);  Z[k] = conj(E) + i conj(O) (k>256), E/O at kk=512-k.
    // Im of bins 0 and 512 dropped (c2r semantics): only kk==0 masks imag.
    {
        float2 x[8];
        #pragma unroll
        for (int k2 = 0; k2 < 8; ++k2) {
            int k  = u + 64 * k2;
            int kk = (k <= 256) ? k : 512 - k;
            float2 Xa = S[kk];
            float2 Xb = S[512 - kk];
            float ar = Xa.x, ai = (kk == 0) ? 0.0f : Xa.y;
            float br = Xb.x, bi = (kk == 0) ? 0.0f : -Xb.y;
            float er  = ar + br, ei  = ai + bi;
            float odr = ar - br, odi = ai - bi;
            float2 t = TWH[kk];
            float or_ = odr * t.x - odi * t.y;
            float oi  = odr * t.y + odi * t.x;
            x[k2] = (k <= 256) ? make_float2(er - oi, ei + or_)
                               : make_float2(er + oi, or_ - ei);
        }
        idft8(x);
        __syncthreads();                    // raw reads done before overwrite
        #pragma unroll
        for (int p = 0; p < 8; ++p) S[9 * u + BR3[p]] = x[p];  // A[j][n2]
        __syncthreads();
    }

    // ---- Stage 2: twiddle w^{k1}, w = e^{2 pi i n2/64}; DFT-8 over k1.
    {
        const int n2 = u & 7;
        const int k0 = u >> 3;
        float2 a[8];
        #pragma unroll
        for (int k1 = 0; k1 < 8; ++k1) a[k1] = S[9 * (k0 + 8 * k1) + n2];
        float ws, wc;
        __sincosf((2.0f * FPI / 64.0f) * (float)n2, &ws, &wc);
        float2 w  = make_float2(wc, ws);
        float2 wk = w;
        a[1] = cmul(a[1], wk);
        #pragma unroll
        for (int k1 = 2; k1 < 8; ++k1) {
            wk = cmul(wk, w);
            a[k1] = cmul(a[k1], wk);
        }
        idft8(a);
        __syncthreads();
        #pragma unroll
        for (int p = 0; p < 8; ++p)
            S[9 * (n2 + 8 * BR3[p]) + k0] = a[p];   // B[m = n2+8*n1][k0]
        __syncthreads();
    }

    // ---- Stage 3: twiddle w^{k0}, w = e^{2 pi i m/512}; DFT-8 over k0.
    {
        const int m = u;
        float2 c[8];
        #pragma unroll
        for (int k0 = 0; k0 < 8; ++k0) c[k0] = S[9 * m + k0];
        float ws, wc;
        __sincosf((2.0f * FPI / 512.0f) * (float)m, &ws, &wc);
        float2 w  = make_float2(wc, ws);
        float2 wk = w;
        c[1] = cmul(c[1], wk);
        #pragma unroll
        for (int k0 = 2; k0 < 8; ++k0) {
            wk = cmul(wk, w);
            c[k0] = cmul(c[k0], wk);
        }
        idft8(c);

        // z[n], n = m + 64*n0. Even/odd unpack: x[2n]=Re, x[2n+1]=Im.
        const int t = tile * 8 + tr;
        __half2* fout = (__half2*)(g_frames + (((size_t)b * NT + t) << 10));
        const float2* w2 = (const float2*)win;
        constexpr float SC = 1.0f / 1024.0f;
        #pragma unroll
        for (int p = 0; p < 8; ++p) {
            int n = m + 64 * BR3[p];
            float2 wv = __ldg(&w2[n]);
            fout[n] = __floats2half2_rn(c[p].x * SC * wv.x, c[p].y * SC * wv.y);
        }
    }
}

// ---------------------------------------------------------------------------
// Kernel 2: overlap-add gather + envelope divide + crop (scalar, high-occ,
// fp16 frame reads, fp32 accumulation).
// ---------------------------------------------------------------------------
__global__ __launch_bounds__(256) void istft_ola_kernel(
    const float* __restrict__ win,
    float* __restrict__ out)
{
    int m = blockIdx.x * 256 + threadIdx.x;   // 0..OUT_LEN-1
    if (m >= OUT_LEN) return;
    int n = m + PAD;
    int q = n >> 8;
    int tlo = max(0, q - 3);
    int thi = min(NT - 1, q);

    float env = 0.0f;
    float acc[BATCH];
    #pragma unroll
    for (int b = 0; b < BATCH; ++b) acc[b] = 0.0f;

    for (int t = tlo; t <= thi; ++t) {
        int w = n - (t << 8);                 // 0..1023
        float wv = __ldg(&win[w]);
        env += wv * wv;
        #pragma unroll
        for (int b = 0; b < BATCH; ++b)
            acc[b] += __half2float(g_frames[(((size_t)b * NT + t) << 10) + w]);
    }

    float inv = 1.0f / fmaxf(env, ENV_EPS);
    #pragma unroll
    for (int b = 0; b < BATCH; ++b)
        out[(size_t)b * OUT_LEN + m] = acc[b] * inv;
}

// ---------------------------------------------------------------------------
extern "C" void kernel_launch(void* const* d_in, const int* in_sizes, int n_in,
                              void* d_out, int out_size)
{
    const float* spec_real = (const float*)d_in[0];
    const float* spec_imag = (const float*)d_in[1];
    const float* window    = (const float*)d_in[2];
    float* out = (float*)d_out;

    istft_fft_kernel<<<BATCH * (NT / 8), 512>>>(spec_real, spec_imag, window);
    istft_ola_kernel<<<OUT_LEN / 256, 256>>>(window, out);
}

// round 6
// speedup vs baseline: 2.3581x; 1.1568x over previous
#include <cuda_runtime.h>
#include <cuda_bf16.h>
#include <cuda_fp16.h>
#include <math.h>

// Problem constants
#define BATCH   8
#define NFREQ   513          // N_FFT/2 + 1
#define NT      4096         // frames
#define HOP     256
#define WIN     1024
#define PAD     384          // (WIN - HOP)/2
#define OUT_LEN 1048576      // (NT-1)*HOP + WIN - 2*PAD
#define ENV_EPS 1e-11f
#define FPI     3.14159265358979323846f
#define R2      0.70710678118654752f

// Scratch: windowed frames [B][T][WIN] in fp16 (67 MB)
__device__ __half g_frames[(size_t)BATCH * NT * WIN];

// ---------------------------------------------------------------------------
// Packed f32x2 complex arithmetic (Blackwell FFMA2 path).
// A complex value lives in one 64-bit register pair: lo = real, hi = imag.
// ---------------------------------------------------------------------------
typedef unsigned long long u64c;

__device__ __forceinline__ u64c mk(float x, float y) {
    u64c r; asm("mov.b64 %0,{%1,%2};" : "=l"(r) : "f"(x), "f"(y)); return r;
}
__device__ __forceinline__ void un(u64c a, float& x, float& y) {
    asm("mov.b64 {%0,%1},%2;" : "=f"(x), "=f"(y) : "l"(a));
}
__device__ __forceinline__ u64c f2add(u64c a, u64c b) {
    u64c r; asm("add.rn.f32x2 %0,%1,%2;" : "=l"(r) : "l"(a), "l"(b)); return r;
}
__device__ __forceinline__ u64c f2mul(u64c a, u64c b) {
    u64c r; asm("mul.rn.f32x2 %0,%1,%2;" : "=l"(r) : "l"(a), "l"(b)); return r;
}
__device__ __forceinline__ u64c f2fma(u64c a, u64c b, u64c c) {
    u64c r; asm("fma.rn.f32x2 %0,%1,%2,%3;" : "=l"(r) : "l"(a), "l"(b), "l"(c)); return r;
}
// a - b  (via fma: b*(-1) + a), n1 = (-1,-1)
__device__ __forceinline__ u64c f2sub(u64c a, u64c b, u64c n1) { return f2fma(b, n1, a); }
// multiply by i: (x,y) -> (-y, x)   (ALU pipe only)
__device__ __forceinline__ u64c muli(u64c a) {
    float x, y; un(a, x, y); return mk(-y, x);
}
// conj: (x,y) -> (x,-y)
__device__ __forceinline__ u64c cconj(u64c a) {
    float x, y; un(a, x, y); return mk(x, -y);
}
// full complex multiply: 1 mul + 1 fma on fma pipe, swaps on ALU pipe
__device__ __forceinline__ u64c cmul(u64c a, u64c b) {
    float bx, by; un(b, bx, by);
    float ax, ay; un(a, ax, ay);
    u64c t = f2mul(mk(-ay, ax), mk(by, by));   // (-ay*by, ax*by)
    return f2fma(a, mk(bx, bx), t);            // (ax*bx - ay*by, ay*bx + ax*by)
}

// 8-point DFT with sign +i (inverse), radix-2 DIF, packed registers.
// Output bit-reversed: slot p holds output index brev3(p) = {0,4,2,6,1,5,3,7}[p].
__device__ __forceinline__ void idft8(u64c x[8], u64c n1, u64c rr)
{
    u64c u, v, d;
    // stage h=4, twiddles 1, (R2+iR2), i, (-R2+iR2)
    u = x[0]; v = x[4];
    x[0] = f2add(u, v);
    x[4] = f2sub(u, v, n1);
    u = x[1]; v = x[5]; d = f2sub(u, v, n1);
    x[1] = f2add(u, v);
    x[5] = f2mul(f2add(d, muli(d)), rr);            // (R2(dx-dy), R2(dx+dy))
    u = x[2]; v = x[6]; d = f2sub(u, v, n1);
    x[2] = f2add(u, v);
    x[6] = muli(d);
    u = x[3]; v = x[7]; d = f2sub(u, v, n1);
    x[3] = f2add(u, v);
    x[7] = f2mul(f2sub(muli(d), d, n1), rr);        // (-R2(dx+dy), R2(dx-dy))
    // stage h=2, twiddles 1, i
    #pragma unroll
    for (int g = 0; g < 8; g += 4) {
        u = x[g]; v = x[g + 2];
        x[g]     = f2add(u, v);
        x[g + 2] = f2sub(u, v, n1);
        u = x[g + 1]; v = x[g + 3]; d = f2sub(u, v, n1);
        x[g + 1] = f2add(u, v);
        x[g + 3] = muli(d);
    }
    // stage h=1
    #pragma unroll
    for (int g = 0; g < 8; g += 2) {
        u = x[g]; v = x[g + 1];
        x[g]     = f2add(u, v);
        x[g + 1] = f2sub(u, v, n1);
    }
}

// ---------------------------------------------------------------------------
// Kernel 1: fused Hermitian pack + 512-pt inverse FFT (3 x radix-8 Stockham,
// 64 threads/transform, 8 transforms per 512-thread block), window + scale,
// fp16 frame output. Packed f32x2 arithmetic throughout.
// ---------------------------------------------------------------------------
#define TSTRIDE 583   // float2 stride per transform

__global__ void __launch_bounds__(512) istft_fft_kernel(
    const float* __restrict__ sr,   // (B, 513, 4096)
    const float* __restrict__ si,
    const float* __restrict__ win)  // (1024,)
{
    __shared__ float2 Sm[8][TSTRIDE];   // per-transform work buffer
    __shared__ float2 TWH[257];         // e^{+i pi k / 512}, k = 0..256

    const int tid = threadIdx.x;

    if (tid < 257) {
        float s, c;
        __sincosf((FPI / 512.0f) * (float)tid, &s, &c);
        TWH[tid] = make_float2(c, s);
    }

    const int blk  = blockIdx.x;        // 0..4095
    const int b    = blk >> 9;          // batch
    const int tile = blk & 511;         // 8 frames per tile
    const size_t base = (size_t)b * NFREQ * NT + (size_t)tile * 8;

    // Coalesced global load: e -> (tl = e&7, k = e>>3)
    for (int e = tid; e < 8 * NFREQ; e += 512) {
        int tl = e & 7;
        int k  = e >> 3;
        size_t g = base + (size_t)k * NT + tl;
        Sm[tl][k] = make_float2(sr[g], si[g]);
    }
    __syncthreads();

    const int u  = tid & 63;    // thread within transform
    const int tr = tid >> 6;    // transform 0..7
    float2* S = Sm[tr];

    const u64c N1 = mk(-1.0f, -1.0f);
    const u64c RR = mk(R2, R2);

    constexpr int BR3[8] = {0, 4, 2, 6, 1, 5, 3, 7};

    // ---- Stage 1: Hermitian pack on the fly + DFT-8 over k2 (stride 64).
    // Z[k] = E + iO (k<=256);  Z[k] = conj(E) + i conj(O) (k>256), E/O at kk=512-k.
    // Im of bins 0 and 512 dropped (c2r semantics): only kk==0 masks imag.
    {
        u64c x[8];
        #pragma unroll
        for (int k2 = 0; k2 < 8; ++k2) {
            int k  = u + 64 * k2;
            int kk = (k <= 256) ? k : 512 - k;
            float ax, ay, bx, by;
            { float2 t = S[kk];        ax = t.x; ay = (kk == 0) ? 0.0f : t.y; }
            { float2 t = S[512 - kk];  bx = t.x; by = (kk == 0) ? 0.0f : -t.y; }
            u64c A  = mk(ax, ay);
            u64c Bc = mk(bx, by);
            u64c E  = f2add(A, Bc);
            u64c Od = f2sub(A, Bc, N1);
            u64c T  = *(const u64c*)&TWH[kk];
            u64c O  = cmul(Od, T);
            // k<=256: Z = E + i*O;  k>256: Z = conj(E) + i*conj(O)
            x[k2] = (k <= 256) ? f2add(E, muli(O))
                               : f2add(cconj(E), muli(cconj(O)));
        }
        idft8(x, N1, RR);
        __syncthreads();                    // raw reads done before overwrite
        #pragma unroll
        for (int p = 0; p < 8; ++p) *(u64c*)&S[9 * u + BR3[p]] = x[p];  // A[j][n2]
        __syncthreads();
    }

    // ---- Stage 2: twiddle w^{k1}, w = e^{2 pi i n2/64}; DFT-8 over k1.
    {
        const int n2 = u & 7;
        const int k0 = u >> 3;
        u64c a[8];
        #pragma unroll
        for (int k1 = 0; k1 < 8; ++k1) a[k1] = *(const u64c*)&S[9 * (k0 + 8 * k1) + n2];
        float ws, wc;
        __sincosf((2.0f * FPI / 64.0f) * (float)n2, &ws, &wc);
        u64c w  = mk(wc, ws);
        u64c wk = w;
        a[1] = cmul(a[1], wk);
        #pragma unroll
        for (int k1 = 2; k1 < 8; ++k1) {
            wk = cmul(wk, w);
            a[k1] = cmul(a[k1], wk);
        }
        idft8(a, N1, RR);
        __syncthreads();
        #pragma unroll
        for (int p = 0; p < 8; ++p)
            *(u64c*)&S[9 * (n2 + 8 * BR3[p]) + k0] = a[p];   // B[m = n2+8*n1][k0]
        __syncthreads();
    }

    // ---- Stage 3: twiddle w^{k0}, w = e^{2 pi i m/512}; DFT-8 over k0.
    {
        const int m = u;
        u64c c[8];
        #pragma unroll
        for (int k0 = 0; k0 < 8; ++k0) c[k0] = *(const u64c*)&S[9 * m + k0];
        float ws, wc;
        __sincosf((2.0f * FPI / 512.0f) * (float)m, &ws, &wc);
        u64c w  = mk(wc, ws);
        u64c wk = w;
        c[1] = cmul(c[1], wk);
        #pragma unroll
        for (int k0 = 2; k0 < 8; ++k0) {
            wk = cmul(wk, w);
            c[k0] = cmul(c[k0], wk);
        }
        idft8(c, N1, RR);

        // z[n], n = m + 64*n0. Even/odd unpack: x[2n]=Re, x[2n+1]=Im.
        const int t = tile * 8 + tr;
        __half2* fout = (__half2*)(g_frames + (((size_t)b * NT + t) << 10));
        const float2* w2 = (const float2*)win;
        const u64c SC2 = mk(1.0f / 1024.0f, 1.0f / 1024.0f);
        #pragma unroll
        for (int p = 0; p < 8; ++p) {
            int n = m + 64 * BR3[p];
            u64c wv = *(const u64c*)&__ldg(&w2[n]);
            u64c o  = f2mul(c[p], f2mul(wv, SC2));
            float ox, oy; un(o, ox, oy);
            fout[n] = __floats2half2_rn(ox, oy);
        }
    }
}

// ---------------------------------------------------------------------------
// Kernel 2: overlap-add gather + envelope divide + crop (scalar, high-occ,
// fp16 frame reads, fp32 accumulation).
// ---------------------------------------------------------------------------
__global__ __launch_bounds__(256) void istft_ola_kernel(
    const float* __restrict__ win,
    float* __restrict__ out)
{
    int m = blockIdx.x * 256 + threadIdx.x;   // 0..OUT_LEN-1
    if (m >= OUT_LEN) return;
    int n = m + PAD;
    int q = n >> 8;
    int tlo = max(0, q - 3);
    int thi = min(NT - 1, q);

    float env = 0.0f;
    float acc[BATCH];
    #pragma unroll
    for (int b = 0; b < BATCH; ++b) acc[b] = 0.0f;

    for (int t = tlo; t <= thi; ++t) {
        int w = n - (t << 8);                 // 0..1023
        float wv = __ldg(&win[w]);
        env += wv * wv;
        #pragma unroll
        for (int b = 0; b < BATCH; ++b)
            acc[b] += __half2float(g_frames[(((size_t)b * NT + t) << 10) + w]);
    }

    float inv = 1.0f / fmaxf(env, ENV_EPS);
    #pragma unroll
    for (int b = 0; b < BATCH; ++b)
        out[(size_t)b * OUT_LEN + m] = acc[b] * inv;
}

// ---------------------------------------------------------------------------
extern "C" void kernel_launch(void* const* d_in, const int* in_sizes, int n_in,
                              void* d_out, int out_size)
{
    const float* spec_real = (const float*)d_in[0];
    const float* spec_imag = (const float*)d_in[1];
    const float* window    = (const float*)d_in[2];
    float* out = (float*)d_out;

    istft_fft_kernel<<<BATCH * (NT / 8), 512>>>(spec_real, spec_imag, window);
    istft_ola_kernel<<<OUT_LEN / 256, 256>>>(window, out);
}